// round 6
// baseline (speedup 1.0000x reference)
#include <cuda_runtime.h>

// DeChunkLayer: B=4, L=4096, D=1024, fp32 in/out.
// h_t = (1-p_s[t]) h_{t-1} + p_s[t]*hidden[b,t,:];  out rows [pos[t],pos[t+1])
// all receive h_t (segment broadcast). 4-kernel chunked scan, CT=16.

#define EPS_F 1e-4f

static constexpr int B = 4;
static constexpr int L = 4096;
static constexpr int D = 1024;
static constexpr int D4 = D / 4;
static constexpr int CT = 16;                 // ranks per chunk
static constexpr int NCHUNK = L / CT;         // 256 (worst case Nb = L)

// Scratch (static device globals)
__device__ float g_Hs[B][L][D];               // chunk-local scan values
__device__ float g_carry[B][NCHUNK][D];       // carry entering each chunk
__device__ float g_ps[B][L];                  // compacted clipped p by rank
__device__ float g_P[B][L];                   // within-chunk inclusive decay prod
__device__ int   g_pos[B][L];                 // token position of rank t
__device__ int   g_Nb[B];                     // boundary count per batch

// ---------------------------------------------------------------------------
// K1: prefix sum of mask; compact clipped p + positions; decay products.
// ---------------------------------------------------------------------------
__global__ __launch_bounds__(1024) void k_setup(const float* __restrict__ bp,
                                                const void* __restrict__ mask) {
    const int b = blockIdx.x;
    const int tid = threadIdx.x;              // 0..1023, 4 tokens each
    const int lane = tid & 31, warp = tid >> 5;

    __shared__ float s_ps[L];                 // 16 KB compacted p
    __shared__ int warp_sums[32];
    __shared__ int sNb;

    // ---- mask format detection (first 4096 words, in-bounds for all layouts)
    const unsigned int* mw = reinterpret_cast<const unsigned int*>(mask);
    int anyFloat = 0, nonBinary = 0;
    for (int i = tid; i < 4096; i += 1024) {
        unsigned int w = mw[i];
        anyFloat  |= (w == 0x3F800000u);
        nonBinary |= (w > 1u);
    }
    int haveFloat  = __syncthreads_or(anyFloat);
    int haveNonBin = __syncthreads_or(nonBinary);
    const int fmt = haveFloat ? 2 : (haveNonBin ? 0 : 1);  // 2=f32, 1=i32, 0=u8

    int cnt[4];
    if (fmt == 0) {
        uchar4 m4 = reinterpret_cast<const uchar4*>(mask)[b * 1024 + tid];
        cnt[0] = m4.x != 0; cnt[1] = m4.y != 0; cnt[2] = m4.z != 0; cnt[3] = m4.w != 0;
    } else {
        uint4 m4 = reinterpret_cast<const uint4*>(mask)[b * 1024 + tid];
        cnt[0] = m4.x != 0; cnt[1] = m4.y != 0; cnt[2] = m4.z != 0; cnt[3] = m4.w != 0;
    }
    int s = cnt[0] + cnt[1] + cnt[2] + cnt[3];

    int incl = s;
#pragma unroll
    for (int o = 1; o < 32; o <<= 1) {
        int v = __shfl_up_sync(0xffffffffu, incl, o);
        if (lane >= o) incl += v;
    }
    if (lane == 31) warp_sums[warp] = incl;
    __syncthreads();
    if (warp == 0) {
        int ws = warp_sums[lane];
#pragma unroll
        for (int o = 1; o < 32; o <<= 1) {
            int v = __shfl_up_sync(0xffffffffu, ws, o);
            if (lane >= o) ws += v;
        }
        warp_sums[lane] = ws;
    }
    __syncthreads();
    int warp_excl = (warp == 0) ? 0 : warp_sums[warp - 1];
    int run = warp_excl + (incl - s);

    const int base = tid * 4;
#pragma unroll
    for (int k = 0; k < 4; ++k) {
        run += cnt[k];
        int l = base + k;
        if (cnt[k]) {
            float p = bp[(b * L + l) * 2 + 1];
            p = fminf(fmaxf(p, EPS_F), 1.0f - EPS_F);
            int t = run - 1;
            g_ps[b][t]  = p;
            s_ps[t]     = p;
            g_pos[b][t] = l;
        }
    }
    if (tid == 1023) { g_Nb[b] = run; sNb = run; }
    __syncthreads();

    const int Nb = sNb;
    // within-chunk inclusive decay products (256 threads x 16 smem reads)
    if (tid < NCHUNK) {
        const int t0 = tid * CT;
        if (t0 < Nb) {
            float prod = 1.0f;
#pragma unroll
            for (int j = 0; j < CT; ++j) {
                int t = t0 + j;
                bool valid = (t < Nb);
                prod *= (1.0f - (valid ? s_ps[t] : 0.0f));
                if (valid) g_P[b][t] = prod;
            }
        }
    }
}

// ---------------------------------------------------------------------------
// K2a: chunk-local EMA scan (carry-in 0), write Hs. Fully unrolled 16 steps.
// ---------------------------------------------------------------------------
__global__ __launch_bounds__(256) void k_chunkscan(const float* __restrict__ hidden) {
    const int b = blockIdx.y;
    const int c = blockIdx.x;
    const int Nb = g_Nb[b];
    const int t0 = c * CT;
    if (t0 >= Nb) return;
    const int nt = min(CT, Nb - t0);

    __shared__ float s_p[CT];
    if (threadIdx.x < CT) {
        int t = t0 + threadIdx.x;
        s_p[threadIdx.x] = (t < Nb) ? g_ps[b][t] : 0.0f;
    }
    __syncthreads();

    const int d4 = threadIdx.x;
    const float4* hid = reinterpret_cast<const float4*>(hidden + b * L * D) + d4;
    float4* Hs = reinterpret_cast<float4*>(&g_Hs[b][0][0]) + d4;

    float4 h = make_float4(0.f, 0.f, 0.f, 0.f);
#pragma unroll
    for (int j = 0; j < CT; ++j) {
        if (j >= nt) break;
        float p = s_p[j];
        float dec = 1.0f - p;
        float4 x = hid[(t0 + j) * D4];
        h.x = fmaf(dec, h.x, p * x.x);
        h.y = fmaf(dec, h.y, p * x.y);
        h.z = fmaf(dec, h.z, p * x.z);
        h.w = fmaf(dec, h.w, p * x.w);
        Hs[(t0 + j) * D4] = h;
    }
}

// ---------------------------------------------------------------------------
// K2b: carry across chunks. Block = (d-slice, b); serial over live chunks,
// loads coalesced + independent of the FMA chain (prefetchable).
// ---------------------------------------------------------------------------
__global__ __launch_bounds__(256) void k_carry() {
    const int b = blockIdx.y;
    const int d = blockIdx.x * 256 + threadIdx.x;   // 0..1023
    const int Nb = g_Nb[b];
    const int nch = (Nb + CT - 1) / CT;

    __shared__ float s_A[NCHUNK];
    for (int c = threadIdx.x; c < nch; c += 256)
        s_A[c] = g_P[b][min((c + 1) * CT, Nb) - 1];
    __syncthreads();

    float carry = 0.0f;
#pragma unroll 4
    for (int c = 0; c < nch; ++c) {
        g_carry[b][c][d] = carry;
        int endt = min((c + 1) * CT, Nb) - 1;
        float U = g_Hs[b][endt][d];
        carry = fmaf(s_A[c], carry, U);
    }
}

// ---------------------------------------------------------------------------
// K3: segment broadcast. One block per rank t:
// o = Hs[t] + P[t]*carry[t/CT]; stream o to rows [pos[t], pos[t+1]).
// ---------------------------------------------------------------------------
__global__ __launch_bounds__(256) void k_out(float* __restrict__ out) {
    const int b = blockIdx.y;
    const int t = blockIdx.x;
    const int Nb = g_Nb[b];
    if (t >= Nb) return;
    const int d4 = threadIdx.x;
    const int c = t >> 4;                     // CT = 16

    const float Pv = g_P[b][t];
    float4 hl = __ldg(reinterpret_cast<const float4*>(&g_Hs[b][t][0]) + d4);
    float4 cy = __ldg(reinterpret_cast<const float4*>(&g_carry[b][c][0]) + d4);
    float4 o;
    o.x = fmaf(Pv, cy.x, hl.x);
    o.y = fmaf(Pv, cy.y, hl.y);
    o.z = fmaf(Pv, cy.z, hl.z);
    o.w = fmaf(Pv, cy.w, hl.w);

    const int l0 = g_pos[b][t];
    const int l1 = (t + 1 < Nb) ? g_pos[b][t + 1] : L;
    int n = l1 - l0;
    float4* dst = reinterpret_cast<float4*>(out) + ((b << 12) + l0) * D4 + d4;
    // independent stores, unrolled for issue density
#pragma unroll 4
    for (int i = 0; i < n; ++i) dst[i * D4] = o;
}

// ---------------------------------------------------------------------------
extern "C" void kernel_launch(void* const* d_in, const int* in_sizes, int n_in,
                              void* d_out, int out_size) {
    const float* hidden = nullptr;
    const float* bp = nullptr;
    const void* mask = nullptr;
    for (int i = 0; i < n_in; ++i) {
        if (in_sizes[i] == B * L * D)      hidden = (const float*)d_in[i];
        else if (in_sizes[i] == B * L * 2) bp = (const float*)d_in[i];
        else if (in_sizes[i] == B * L)     mask = d_in[i];
    }
    float* out = (float*)d_out;

    k_setup<<<B, 1024>>>(bp, mask);
    k_chunkscan<<<dim3(NCHUNK, B), 256>>>(hidden);
    k_carry<<<dim3(D / 256, B), 256>>>();
    k_out<<<dim3(L, B), 256>>>(out);
}

// round 8
// speedup vs baseline: 1.1733x; 1.1733x over previous
#include <cuda_runtime.h>

// DeChunkLayer: B=4, L=4096, D=1024, fp32 in/out.
// h_t = (1-p_s[t]) h_{t-1} + p_s[t]*hidden[b,t,:];  out rows [pos[t],pos[t+1])
// all receive h_t. 4 kernels: setup / chunk-aggregate / warp-affine carry /
// rescan+broadcast. No Hs materialization (hidden re-read is L2-hot).

#define EPS_F 1e-4f

static constexpr int B = 4;
static constexpr int L = 4096;
static constexpr int D = 1024;
static constexpr int D4 = D / 4;
static constexpr int CT = 32;                 // ranks per chunk
static constexpr int NCHUNK = L / CT;         // 128 (worst case Nb = L)
static constexpr int CPL = NCHUNK / 32;       // 4 chunks per lane in carry scan

// Scratch (static device globals)
__device__ float g_hend[B][NCHUNK][D];        // chunk-end scan state (1 MB)
__device__ float g_carry[B][NCHUNK][D];       // carry entering each chunk (2 MB)
__device__ float g_ps[B][L];                  // compacted clipped p by rank
__device__ float g_P[B][L];                   // within-chunk inclusive decay prod
__device__ int   g_pos[B][L];                 // token position of rank t
__device__ int   g_Nb[B];                     // boundary count per batch

// ---------------------------------------------------------------------------
// K1: prefix sum of mask; compact clipped p + positions; decay products.
// ---------------------------------------------------------------------------
__global__ __launch_bounds__(1024) void k_setup(const float* __restrict__ bp,
                                                const void* __restrict__ mask) {
    const int b = blockIdx.x;
    const int tid = threadIdx.x;              // 0..1023, 4 tokens each
    const int lane = tid & 31, warp = tid >> 5;

    __shared__ float s_ps[L];                 // 16 KB compacted p
    __shared__ int warp_sums[32];
    __shared__ int sNb;

    // ---- mask format detection (first 4096 words, in-bounds for all layouts)
    const unsigned int* mw = reinterpret_cast<const unsigned int*>(mask);
    int anyFloat = 0, nonBinary = 0;
    for (int i = tid; i < 4096; i += 1024) {
        unsigned int w = mw[i];
        anyFloat  |= (w == 0x3F800000u);
        nonBinary |= (w > 1u);
    }
    int haveFloat  = __syncthreads_or(anyFloat);
    int haveNonBin = __syncthreads_or(nonBinary);
    const int fmt = haveFloat ? 2 : (haveNonBin ? 0 : 1);  // 2=f32, 1=i32, 0=u8

    int cnt[4];
    if (fmt == 0) {
        uchar4 m4 = reinterpret_cast<const uchar4*>(mask)[b * 1024 + tid];
        cnt[0] = m4.x != 0; cnt[1] = m4.y != 0; cnt[2] = m4.z != 0; cnt[3] = m4.w != 0;
    } else {
        uint4 m4 = reinterpret_cast<const uint4*>(mask)[b * 1024 + tid];
        cnt[0] = m4.x != 0; cnt[1] = m4.y != 0; cnt[2] = m4.z != 0; cnt[3] = m4.w != 0;
    }
    int s = cnt[0] + cnt[1] + cnt[2] + cnt[3];

    int incl = s;
#pragma unroll
    for (int o = 1; o < 32; o <<= 1) {
        int v = __shfl_up_sync(0xffffffffu, incl, o);
        if (lane >= o) incl += v;
    }
    if (lane == 31) warp_sums[warp] = incl;
    __syncthreads();
    if (warp == 0) {
        int ws = warp_sums[lane];
#pragma unroll
        for (int o = 1; o < 32; o <<= 1) {
            int v = __shfl_up_sync(0xffffffffu, ws, o);
            if (lane >= o) ws += v;
        }
        warp_sums[lane] = ws;
    }
    __syncthreads();
    int warp_excl = (warp == 0) ? 0 : warp_sums[warp - 1];
    int run = warp_excl + (incl - s);

    const int base = tid * 4;
#pragma unroll
    for (int k = 0; k < 4; ++k) {
        run += cnt[k];
        int l = base + k;
        if (cnt[k]) {
            float p = bp[(b * L + l) * 2 + 1];
            p = fminf(fmaxf(p, EPS_F), 1.0f - EPS_F);
            int t = run - 1;
            g_ps[b][t]  = p;
            s_ps[t]     = p;
            g_pos[b][t] = l;
        }
    }
    if (tid == 1023) { g_Nb[b] = run; sNb = run; }
    __syncthreads();

    const int Nb = sNb;
    // within-chunk inclusive decay products (NCHUNK threads x CT smem reads)
    if (tid < NCHUNK) {
        const int t0 = tid * CT;
        if (t0 < Nb) {
            float prod = 1.0f;
#pragma unroll
            for (int j = 0; j < CT; ++j) {
                int t = t0 + j;
                bool valid = (t < Nb);
                prod *= (1.0f - (valid ? s_ps[t] : 0.0f));
                if (valid) g_P[b][t] = prod;
            }
        }
    }
}

// ---------------------------------------------------------------------------
// K2: chunk-local scan in registers; write only chunk-end state.
// ---------------------------------------------------------------------------
__global__ __launch_bounds__(256) void k_scanagg(const float* __restrict__ hidden) {
    const int b = blockIdx.y;
    const int c = blockIdx.x;
    const int Nb = g_Nb[b];
    const int t0 = c * CT;
    if (t0 >= Nb) return;
    const int nt = min(CT, Nb - t0);

    __shared__ float s_p[CT];
    if (threadIdx.x < CT) {
        int t = t0 + threadIdx.x;
        s_p[threadIdx.x] = (t < Nb) ? g_ps[b][t] : 0.0f;
    }
    __syncthreads();

    const int d4 = threadIdx.x;
    const float4* hid = reinterpret_cast<const float4*>(hidden + b * L * D) + d4;

    float4 h = make_float4(0.f, 0.f, 0.f, 0.f);
#pragma unroll 8
    for (int j = 0; j < CT; ++j) {
        if (j >= nt) break;
        float p = s_p[j];
        float dec = 1.0f - p;
        float4 x = hid[(t0 + j) * D4];
        h.x = fmaf(dec, h.x, p * x.x);
        h.y = fmaf(dec, h.y, p * x.y);
        h.z = fmaf(dec, h.z, p * x.z);
        h.w = fmaf(dec, h.w, p * x.w);
    }
    reinterpret_cast<float4*>(&g_hend[b][c][0])[d4] = h;
}

// ---------------------------------------------------------------------------
// K3: carry across chunks. Warp per (b,d); 4 chunks per lane, affine
// compose + 5-step shuffle scan. Dead chunks are identity (A=1, U=0).
// ---------------------------------------------------------------------------
__global__ __launch_bounds__(256) void k_carry() {
    const int warp = threadIdx.x >> 5;
    const int lane = threadIdx.x & 31;
    const int g = blockIdx.x * 8 + warp;      // 0..4095 = (b,d)
    const int b = g >> 10;
    const int d = g & 1023;
    const int Nb = g_Nb[b];

    float a[CPL], u[CPL];
    float A = 1.0f, U = 0.0f;
#pragma unroll
    for (int k = 0; k < CPL; ++k) {
        const int c = CPL * lane + k;
        const int t0 = c * CT;
        if (t0 < Nb) {
            int endt = min(t0 + CT, Nb) - 1;
            a[k] = g_P[b][endt];
            u[k] = g_hend[b][c][d];
        } else {
            a[k] = 1.0f; u[k] = 0.0f;
        }
        U = fmaf(a[k], U, u[k]);
        A *= a[k];
    }

    // inclusive warp scan with affine composition
#pragma unroll
    for (int o = 1; o < 32; o <<= 1) {
        float pa = __shfl_up_sync(0xffffffffu, A, o);
        float pu = __shfl_up_sync(0xffffffffu, U, o);
        if (lane >= o) {
            U = fmaf(A, pu, U);
            A = A * pa;
        }
    }
    // exclusive prefix entering this lane's first chunk (initial state is 0,
    // so the carry value is just U of the exclusive prefix)
    float s = __shfl_up_sync(0xffffffffu, U, 1);
    if (lane == 0) s = 0.0f;

#pragma unroll
    for (int k = 0; k < CPL; ++k) {
        const int c = CPL * lane + k;
        g_carry[b][c][d] = s;
        s = fmaf(a[k], s, u[k]);
    }
}

// ---------------------------------------------------------------------------
// K4: rescan from carry + segment broadcast. Block per live chunk; hidden
// re-reads are L2-hot; long coalesced store streams.
// ---------------------------------------------------------------------------
__global__ __launch_bounds__(256) void k_rescan(const float* __restrict__ hidden,
                                                float* __restrict__ out) {
    const int b = blockIdx.y;
    const int c = blockIdx.x;
    const int Nb = g_Nb[b];
    const int t0 = c * CT;
    if (t0 >= Nb) return;
    const int nt = min(CT, Nb - t0);
    const int d4 = threadIdx.x;

    __shared__ float s_p[CT];
    __shared__ int s_pos[CT + 1];
    if (threadIdx.x < CT) {
        int t = t0 + threadIdx.x;
        s_p[threadIdx.x]   = (t < Nb) ? g_ps[b][t] : 0.0f;
        s_pos[threadIdx.x] = (t < Nb) ? g_pos[b][t] : L;
    }
    if (threadIdx.x == 0) s_pos[CT] = (t0 + CT < Nb) ? g_pos[b][t0 + CT] : L;
    __syncthreads();

    const float4* hid = reinterpret_cast<const float4*>(hidden + b * L * D) + d4;
    float4* outp = reinterpret_cast<float4*>(out) + (b << 12) * D4 + d4;

    float4 h = reinterpret_cast<const float4*>(&g_carry[b][c][0])[d4];
#pragma unroll 4
    for (int j = 0; j < CT; ++j) {
        if (j >= nt) break;
        float p = s_p[j];
        float dec = 1.0f - p;
        float4 x = hid[(t0 + j) * D4];
        h.x = fmaf(dec, h.x, p * x.x);
        h.y = fmaf(dec, h.y, p * x.y);
        h.z = fmaf(dec, h.z, p * x.z);
        h.w = fmaf(dec, h.w, p * x.w);
        const int l0 = s_pos[j];
        const int n = s_pos[j + 1] - l0;
        float4* dst = outp + l0 * D4;
#pragma unroll 4
        for (int i = 0; i < n; ++i) dst[i * D4] = h;
    }
}

// ---------------------------------------------------------------------------
extern "C" void kernel_launch(void* const* d_in, const int* in_sizes, int n_in,
                              void* d_out, int out_size) {
    const float* hidden = nullptr;
    const float* bp = nullptr;
    const void* mask = nullptr;
    for (int i = 0; i < n_in; ++i) {
        if (in_sizes[i] == B * L * D)      hidden = (const float*)d_in[i];
        else if (in_sizes[i] == B * L * 2) bp = (const float*)d_in[i];
        else if (in_sizes[i] == B * L)     mask = d_in[i];
    }
    float* out = (float*)d_out;

    k_setup<<<B, 1024>>>(bp, mask);
    k_scanagg<<<dim3(NCHUNK, B), 256>>>(hidden);
    k_carry<<<B * D / 8, 256>>>();
    k_rescan<<<dim3(NCHUNK, B), 256>>>(hidden, out);
}

// round 9
// speedup vs baseline: 1.3551x; 1.1550x over previous
#include <cuda_runtime.h>

// DeChunkLayer: B=4, L=4096, D=1024, fp32 in/out.
// h_t = (1-p_s[t]) h_{t-1} + p_s[t]*hidden[b,t,:];  out rows [pos[t],pos[t+1])
// all receive h_t. Kernels: setup / chunk-aggregate (D-sliced) / warp-affine
// carry / rescan+broadcast (D-sliced). No Hs materialization.

#define EPS_F 1e-4f

static constexpr int B = 4;
static constexpr int L = 4096;
static constexpr int D = 1024;
static constexpr int D4 = D / 4;
static constexpr int CT = 16;                 // ranks per chunk
static constexpr int NCHUNK = L / CT;         // 256 (worst case Nb = L)
static constexpr int CPL = NCHUNK / 32;       // 8 chunks per lane in carry scan
static constexpr int Z = 4;                   // D slices per chunk
static constexpr int TPZ = D4 / Z;            // 64 threads per slice block

// Scratch (static device globals)
__device__ float g_hend[B][NCHUNK][D];        // chunk-end scan state
__device__ float g_carry[B][NCHUNK][D];       // carry entering each chunk
__device__ float g_ps[B][L];                  // compacted clipped p by rank
__device__ float g_P[B][L];                   // within-chunk inclusive decay prod
__device__ int   g_pos[B][L];                 // token position of rank t
__device__ int   g_Nb[B];                     // boundary count per batch

// ---------------------------------------------------------------------------
// K1: prefix sum of mask; compact clipped p + positions; decay products.
// ---------------------------------------------------------------------------
__global__ __launch_bounds__(1024) void k_setup(const float* __restrict__ bp,
                                                const void* __restrict__ mask) {
    const int b = blockIdx.x;
    const int tid = threadIdx.x;              // 0..1023, 4 tokens each
    const int lane = tid & 31, warp = tid >> 5;

    __shared__ float s_ps[L];                 // 16 KB compacted p
    __shared__ int warp_sums[32];
    __shared__ int sNb;

    // ---- mask format detection (first 4096 words, in-bounds for all layouts)
    const unsigned int* mw = reinterpret_cast<const unsigned int*>(mask);
    int anyFloat = 0, nonBinary = 0;
    for (int i = tid; i < 4096; i += 1024) {
        unsigned int w = mw[i];
        anyFloat  |= (w == 0x3F800000u);
        nonBinary |= (w > 1u);
    }
    int haveFloat  = __syncthreads_or(anyFloat);
    int haveNonBin = __syncthreads_or(nonBinary);
    const int fmt = haveFloat ? 2 : (haveNonBin ? 0 : 1);  // 2=f32, 1=i32, 0=u8

    int cnt[4];
    if (fmt == 0) {
        uchar4 m4 = reinterpret_cast<const uchar4*>(mask)[b * 1024 + tid];
        cnt[0] = m4.x != 0; cnt[1] = m4.y != 0; cnt[2] = m4.z != 0; cnt[3] = m4.w != 0;
    } else {
        uint4 m4 = reinterpret_cast<const uint4*>(mask)[b * 1024 + tid];
        cnt[0] = m4.x != 0; cnt[1] = m4.y != 0; cnt[2] = m4.z != 0; cnt[3] = m4.w != 0;
    }
    int s = cnt[0] + cnt[1] + cnt[2] + cnt[3];

    int incl = s;
#pragma unroll
    for (int o = 1; o < 32; o <<= 1) {
        int v = __shfl_up_sync(0xffffffffu, incl, o);
        if (lane >= o) incl += v;
    }
    if (lane == 31) warp_sums[warp] = incl;
    __syncthreads();
    if (warp == 0) {
        int ws = warp_sums[lane];
#pragma unroll
        for (int o = 1; o < 32; o <<= 1) {
            int v = __shfl_up_sync(0xffffffffu, ws, o);
            if (lane >= o) ws += v;
        }
        warp_sums[lane] = ws;
    }
    __syncthreads();
    int warp_excl = (warp == 0) ? 0 : warp_sums[warp - 1];
    int run = warp_excl + (incl - s);

    const int base = tid * 4;
#pragma unroll
    for (int k = 0; k < 4; ++k) {
        run += cnt[k];
        int l = base + k;
        if (cnt[k]) {
            float p = bp[(b * L + l) * 2 + 1];
            p = fminf(fmaxf(p, EPS_F), 1.0f - EPS_F);
            int t = run - 1;
            g_ps[b][t]  = p;
            s_ps[t]     = p;
            g_pos[b][t] = l;
        }
    }
    if (tid == 1023) { g_Nb[b] = run; sNb = run; }
    __syncthreads();

    const int Nb = sNb;
    // within-chunk inclusive decay products (NCHUNK threads x CT smem reads)
    if (tid < NCHUNK) {
        const int t0 = tid * CT;
        if (t0 < Nb) {
            float prod = 1.0f;
#pragma unroll
            for (int j = 0; j < CT; ++j) {
                int t = t0 + j;
                bool valid = (t < Nb);
                prod *= (1.0f - (valid ? s_ps[t] : 0.0f));
                if (valid) g_P[b][t] = prod;
            }
        }
    }
}

// ---------------------------------------------------------------------------
// K2: chunk-local scan in registers; write only chunk-end state. D-sliced.
// ---------------------------------------------------------------------------
__global__ __launch_bounds__(TPZ) void k_scanagg(const float* __restrict__ hidden) {
    const int b = blockIdx.y;
    const int c = blockIdx.x;
    const int z = blockIdx.z;
    const int Nb = g_Nb[b];
    const int t0 = c * CT;
    if (t0 >= Nb) return;
    const int nt = min(CT, Nb - t0);

    __shared__ float s_p[CT];
    if (threadIdx.x < CT) {
        int t = t0 + threadIdx.x;
        s_p[threadIdx.x] = (t < Nb) ? g_ps[b][t] : 0.0f;
    }
    __syncthreads();

    const int d4 = z * TPZ + threadIdx.x;
    const float4* hid = reinterpret_cast<const float4*>(hidden + b * L * D) + d4;

    float4 h = make_float4(0.f, 0.f, 0.f, 0.f);
#pragma unroll
    for (int j = 0; j < CT; ++j) {
        if (j >= nt) break;
        float p = s_p[j];
        float dec = 1.0f - p;
        float4 x = hid[(t0 + j) * D4];
        h.x = fmaf(dec, h.x, p * x.x);
        h.y = fmaf(dec, h.y, p * x.y);
        h.z = fmaf(dec, h.z, p * x.z);
        h.w = fmaf(dec, h.w, p * x.w);
    }
    reinterpret_cast<float4*>(&g_hend[b][c][0])[d4] = h;
}

// ---------------------------------------------------------------------------
// K3: carry across chunks. Warp per (b,d); 8 chunks per lane, affine
// compose + 5-step shuffle scan. Dead chunks are identity (A=1, U=0).
// ---------------------------------------------------------------------------
__global__ __launch_bounds__(256) void k_carry() {
    const int warp = threadIdx.x >> 5;
    const int lane = threadIdx.x & 31;
    const int g = blockIdx.x * 8 + warp;      // 0..4095 = (b,d)
    const int b = g >> 10;
    const int d = g & 1023;
    const int Nb = g_Nb[b];

    float a[CPL], u[CPL];
    float A = 1.0f, U = 0.0f;
#pragma unroll
    for (int k = 0; k < CPL; ++k) {
        const int c = CPL * lane + k;
        const int t0 = c * CT;
        if (t0 < Nb) {
            int endt = min(t0 + CT, Nb) - 1;
            a[k] = g_P[b][endt];
            u[k] = g_hend[b][c][d];
        } else {
            a[k] = 1.0f; u[k] = 0.0f;
        }
        U = fmaf(a[k], U, u[k]);
        A *= a[k];
    }

    // inclusive warp scan with affine composition
#pragma unroll
    for (int o = 1; o < 32; o <<= 1) {
        float pa = __shfl_up_sync(0xffffffffu, A, o);
        float pu = __shfl_up_sync(0xffffffffu, U, o);
        if (lane >= o) {
            U = fmaf(A, pu, U);
            A = A * pa;
        }
    }
    // exclusive prefix entering this lane's first chunk
    float s = __shfl_up_sync(0xffffffffu, U, 1);
    if (lane == 0) s = 0.0f;

#pragma unroll
    for (int k = 0; k < CPL; ++k) {
        const int c = CPL * lane + k;
        g_carry[b][c][d] = s;
        s = fmaf(a[k], s, u[k]);
    }
}

// ---------------------------------------------------------------------------
// K4: rescan from carry + segment broadcast. D-sliced: block = (chunk, b, z).
// hidden re-reads are L2-hot; long coalesced store streams.
// ---------------------------------------------------------------------------
__global__ __launch_bounds__(TPZ) void k_rescan(const float* __restrict__ hidden,
                                                float* __restrict__ out) {
    const int b = blockIdx.y;
    const int c = blockIdx.x;
    const int z = blockIdx.z;
    const int Nb = g_Nb[b];
    const int t0 = c * CT;
    if (t0 >= Nb) return;
    const int nt = min(CT, Nb - t0);
    const int d4 = z * TPZ + threadIdx.x;

    __shared__ float s_p[CT];
    __shared__ int s_pos[CT + 1];
    if (threadIdx.x < CT) {
        int t = t0 + threadIdx.x;
        s_p[threadIdx.x]   = (t < Nb) ? g_ps[b][t] : 0.0f;
        s_pos[threadIdx.x] = (t < Nb) ? g_pos[b][t] : L;
    }
    if (threadIdx.x == 0) s_pos[CT] = (t0 + CT < Nb) ? g_pos[b][t0 + CT] : L;
    __syncthreads();

    const float4* hid = reinterpret_cast<const float4*>(hidden + b * L * D) + d4;
    float4* outp = reinterpret_cast<float4*>(out) + (b << 12) * D4 + d4;

    float4 h = reinterpret_cast<const float4*>(&g_carry[b][c][0])[d4];
#pragma unroll
    for (int j = 0; j < CT; ++j) {
        if (j >= nt) break;
        float p = s_p[j];
        float dec = 1.0f - p;
        float4 x = hid[(t0 + j) * D4];
        h.x = fmaf(dec, h.x, p * x.x);
        h.y = fmaf(dec, h.y, p * x.y);
        h.z = fmaf(dec, h.z, p * x.z);
        h.w = fmaf(dec, h.w, p * x.w);
        const int l0 = s_pos[j];
        const int n = s_pos[j + 1] - l0;
        float4* dst = outp + l0 * D4;
#pragma unroll 4
        for (int i = 0; i < n; ++i) dst[i * D4] = h;
    }
}

// ---------------------------------------------------------------------------
extern "C" void kernel_launch(void* const* d_in, const int* in_sizes, int n_in,
                              void* d_out, int out_size) {
    const float* hidden = nullptr;
    const float* bp = nullptr;
    const void* mask = nullptr;
    for (int i = 0; i < n_in; ++i) {
        if (in_sizes[i] == B * L * D)      hidden = (const float*)d_in[i];
        else if (in_sizes[i] == B * L * 2) bp = (const float*)d_in[i];
        else if (in_sizes[i] == B * L)     mask = d_in[i];
    }
    float* out = (float*)d_out;

    k_setup<<<B, 1024>>>(bp, mask);
    k_scanagg<<<dim3(NCHUNK, B, Z), TPZ>>>(hidden);
    k_carry<<<B * D / 8, 256>>>();
    k_rescan<<<dim3(NCHUNK, B, Z), TPZ>>>(hidden, out);
}

// round 12
// speedup vs baseline: 1.4277x; 1.0536x over previous
#include <cuda_runtime.h>

// DeChunkLayer: B=4, L=4096, D=1024, fp32 in/out.
// h_t = (1-p_s[t]) h_{t-1} + p_s[t]*hidden[b,t,:];  out rows [pos[t],pos[t+1])
// all receive h_t. Kernels: setup / chunk-aggregate (D-sliced) / warp-affine
// carry / rescan+broadcast (D-sliced). Branchless padded loops + x preload.

#define EPS_F 1e-4f

static constexpr int B = 4;
static constexpr int L = 4096;
static constexpr int D = 1024;
static constexpr int D4 = D / 4;
static constexpr int CT = 16;                 // ranks per chunk
static constexpr int NCHUNK = L / CT;         // 256 (worst case Nb = L)
static constexpr int CPL = NCHUNK / 32;       // 8 chunks per lane in carry scan
static constexpr int Z = 4;                   // D slices per chunk
static constexpr int TPZ = D4 / Z;            // 64 threads per slice block

// Scratch (static device globals)
__device__ float g_hend[B][NCHUNK][D];        // chunk-end scan state
__device__ float g_carry[B][NCHUNK][D];       // carry entering each chunk
__device__ float g_ps[B][L];                  // compacted clipped p by rank
__device__ float g_P[B][L];                   // within-chunk inclusive decay prod
__device__ int   g_pos[B][L];                 // token position of rank t
__device__ int   g_Nb[B];                     // boundary count per batch

// ---------------------------------------------------------------------------
// K1: prefix sum of mask; compact clipped p + positions; decay products.
// ---------------------------------------------------------------------------
__global__ __launch_bounds__(1024) void k_setup(const float* __restrict__ bp,
                                                const void* __restrict__ mask) {
    const int b = blockIdx.x;
    const int tid = threadIdx.x;              // 0..1023, 4 tokens each
    const int lane = tid & 31, warp = tid >> 5;

    __shared__ float s_ps[L];                 // 16 KB compacted p
    __shared__ int warp_sums[32];
    __shared__ int sNb;

    // ---- mask format detection (first 4096 words, in-bounds for all layouts)
    const unsigned int* mw = reinterpret_cast<const unsigned int*>(mask);
    int anyFloat = 0, nonBinary = 0;
    for (int i = tid; i < 4096; i += 1024) {
        unsigned int w = mw[i];
        anyFloat  |= (w == 0x3F800000u);
        nonBinary |= (w > 1u);
    }
    int haveFloat  = __syncthreads_or(anyFloat);
    int haveNonBin = __syncthreads_or(nonBinary);
    const int fmt = haveFloat ? 2 : (haveNonBin ? 0 : 1);  // 2=f32, 1=i32, 0=u8

    int cnt[4];
    if (fmt == 0) {
        uchar4 m4 = reinterpret_cast<const uchar4*>(mask)[b * 1024 + tid];
        cnt[0] = m4.x != 0; cnt[1] = m4.y != 0; cnt[2] = m4.z != 0; cnt[3] = m4.w != 0;
    } else {
        uint4 m4 = reinterpret_cast<const uint4*>(mask)[b * 1024 + tid];
        cnt[0] = m4.x != 0; cnt[1] = m4.y != 0; cnt[2] = m4.z != 0; cnt[3] = m4.w != 0;
    }
    int s = cnt[0] + cnt[1] + cnt[2] + cnt[3];

    int incl = s;
#pragma unroll
    for (int o = 1; o < 32; o <<= 1) {
        int v = __shfl_up_sync(0xffffffffu, incl, o);
        if (lane >= o) incl += v;
    }
    if (lane == 31) warp_sums[warp] = incl;
    __syncthreads();
    if (warp == 0) {
        int ws = warp_sums[lane];
#pragma unroll
        for (int o = 1; o < 32; o <<= 1) {
            int v = __shfl_up_sync(0xffffffffu, ws, o);
            if (lane >= o) ws += v;
        }
        warp_sums[lane] = ws;
    }
    __syncthreads();
    int warp_excl = (warp == 0) ? 0 : warp_sums[warp - 1];
    int run = warp_excl + (incl - s);

    const int base = tid * 4;
#pragma unroll
    for (int k = 0; k < 4; ++k) {
        run += cnt[k];
        int l = base + k;
        if (cnt[k]) {
            float p = bp[(b * L + l) * 2 + 1];
            p = fminf(fmaxf(p, EPS_F), 1.0f - EPS_F);
            int t = run - 1;
            g_ps[b][t]  = p;
            s_ps[t]     = p;
            g_pos[b][t] = l;
        }
    }
    if (tid == 1023) { g_Nb[b] = run; sNb = run; }
    __syncthreads();

    const int Nb = sNb;
    // within-chunk inclusive decay products (NCHUNK threads x CT smem reads)
    if (tid < NCHUNK) {
        const int t0 = tid * CT;
        if (t0 < Nb) {
            float prod = 1.0f;
#pragma unroll
            for (int j = 0; j < CT; ++j) {
                int t = t0 + j;
                bool valid = (t < Nb);
                prod *= (1.0f - (valid ? s_ps[t] : 0.0f));
                if (valid) g_P[b][t] = prod;
            }
        }
    }
}

// ---------------------------------------------------------------------------
// K2: chunk-local scan in registers; write only chunk-end state. D-sliced.
// Branchless (p=0 padding), all CT loads preloaded for MLP.
// ---------------------------------------------------------------------------
__global__ __launch_bounds__(TPZ) void k_scanagg(const float* __restrict__ hidden) {
    const int b = blockIdx.y;
    const int c = blockIdx.x;
    const int z = blockIdx.z;
    const int Nb = g_Nb[b];
    const int t0 = c * CT;
    if (t0 >= Nb) return;

    __shared__ float s_p[CT];
    if (threadIdx.x < CT) {
        int t = t0 + threadIdx.x;
        s_p[threadIdx.x] = (t < Nb) ? g_ps[b][t] : 0.0f;   // p=0 => identity step
    }
    __syncthreads();

    const int d4 = z * TPZ + threadIdx.x;
    const float4* hid = reinterpret_cast<const float4*>(hidden + b * L * D) + d4;

    float4 xr[CT];
#pragma unroll
    for (int j = 0; j < CT; ++j) xr[j] = hid[(t0 + j) * D4];

    float4 h = make_float4(0.f, 0.f, 0.f, 0.f);
#pragma unroll
    for (int j = 0; j < CT; ++j) {
        float p = s_p[j];
        float dec = 1.0f - p;
        h.x = fmaf(dec, h.x, p * xr[j].x);
        h.y = fmaf(dec, h.y, p * xr[j].y);
        h.z = fmaf(dec, h.z, p * xr[j].z);
        h.w = fmaf(dec, h.w, p * xr[j].w);
    }
    reinterpret_cast<float4*>(&g_hend[b][c][0])[d4] = h;
}

// ---------------------------------------------------------------------------
// K3: carry across chunks. Warp per (b,d); 8 chunks per lane, affine
// compose + 5-step shuffle scan. Dead chunks are identity (A=1, U=0).
// ---------------------------------------------------------------------------
__global__ __launch_bounds__(256) void k_carry() {
    const int warp = threadIdx.x >> 5;
    const int lane = threadIdx.x & 31;
    const int g = blockIdx.x * 8 + warp;      // 0..4095 = (b,d)
    const int b = g >> 10;
    const int d = g & 1023;
    const int Nb = g_Nb[b];

    float a[CPL], u[CPL];
    float A = 1.0f, U = 0.0f;
#pragma unroll
    for (int k = 0; k < CPL; ++k) {
        const int c = CPL * lane + k;
        const int t0 = c * CT;
        if (t0 < Nb) {
            int endt = min(t0 + CT, Nb) - 1;
            a[k] = g_P[b][endt];
            u[k] = g_hend[b][c][d];
        } else {
            a[k] = 1.0f; u[k] = 0.0f;
        }
        U = fmaf(a[k], U, u[k]);
        A *= a[k];
    }

    // inclusive warp scan with affine composition
#pragma unroll
    for (int o = 1; o < 32; o <<= 1) {
        float pa = __shfl_up_sync(0xffffffffu, A, o);
        float pu = __shfl_up_sync(0xffffffffu, U, o);
        if (lane >= o) {
            U = fmaf(A, pu, U);
            A = A * pa;
        }
    }
    // exclusive prefix entering this lane's first chunk
    float s = __shfl_up_sync(0xffffffffu, U, 1);
    if (lane == 0) s = 0.0f;

#pragma unroll
    for (int k = 0; k < CPL; ++k) {
        const int c = CPL * lane + k;
        g_carry[b][c][d] = s;
        s = fmaf(a[k], s, u[k]);
    }
}

// ---------------------------------------------------------------------------
// K4: rescan from carry + segment broadcast. D-sliced: block = (chunk, b, z).
// Branchless padded iterations; all CT x-loads preloaded (MLP=16).
// ---------------------------------------------------------------------------
__global__ __launch_bounds__(TPZ) void k_rescan(const float* __restrict__ hidden,
                                                float* __restrict__ out) {
    const int b = blockIdx.y;
    const int c = blockIdx.x;
    const int z = blockIdx.z;
    const int Nb = g_Nb[b];
    const int t0 = c * CT;
    if (t0 >= Nb) return;
    const int d4 = z * TPZ + threadIdx.x;

    __shared__ float s_p[CT];
    __shared__ int s_pos[CT + 1];
    if (threadIdx.x < CT) {
        int t = t0 + threadIdx.x;
        s_p[threadIdx.x]   = (t < Nb) ? g_ps[b][t] : 0.0f;  // identity pad
        s_pos[threadIdx.x] = (t < Nb) ? g_pos[b][t] : L;    // empty segment pad
    }
    if (threadIdx.x == 0) s_pos[CT] = (t0 + CT < Nb) ? g_pos[b][t0 + CT] : L;
    __syncthreads();

    const float4* hid = reinterpret_cast<const float4*>(hidden + b * L * D) + d4;
    float4* outp = reinterpret_cast<float4*>(out) + (b << 12) * D4 + d4;

    float4 xr[CT];
#pragma unroll
    for (int j = 0; j < CT; ++j) xr[j] = hid[(t0 + j) * D4];

    float4 h = reinterpret_cast<const float4*>(&g_carry[b][c][0])[d4];
#pragma unroll
    for (int j = 0; j < CT; ++j) {
        float p = s_p[j];
        float dec = 1.0f - p;
        h.x = fmaf(dec, h.x, p * xr[j].x);
        h.y = fmaf(dec, h.y, p * xr[j].y);
        h.z = fmaf(dec, h.z, p * xr[j].z);
        h.w = fmaf(dec, h.w, p * xr[j].w);
        const int l0 = s_pos[j];
        const int n = s_pos[j + 1] - l0;
        float4* dst = outp + l0 * D4;
#pragma unroll 4
        for (int i = 0; i < n; ++i) dst[i * D4] = h;
    }
}

// ---------------------------------------------------------------------------
extern "C" void kernel_launch(void* const* d_in, const int* in_sizes, int n_in,
                              void* d_out, int out_size) {
    const float* hidden = nullptr;
    const float* bp = nullptr;
    const void* mask = nullptr;
    for (int i = 0; i < n_in; ++i) {
        if (in_sizes[i] == B * L * D)      hidden = (const float*)d_in[i];
        else if (in_sizes[i] == B * L * 2) bp = (const float*)d_in[i];
        else if (in_sizes[i] == B * L)     mask = d_in[i];
    }
    float* out = (float*)d_out;

    k_setup<<<B, 1024>>>(bp, mask);
    k_scanagg<<<dim3(NCHUNK, B, Z), TPZ>>>(hidden);
    k_carry<<<B * D / 8, 256>>>();
    k_rescan<<<dim3(NCHUNK, B, Z), TPZ>>>(hidden, out);
}